// round 13
// baseline (speedup 1.0000x reference)
#include <cuda_runtime.h>
#include <math.h>
#include <stdint.h>

// Problem constants
#define BB 2
#define TT 2048
#define DD 2048
#define NH 32
#define NKV 8
#define DH 64
#define GG 4   // NH / NKV

// Scratch (device globals)
__device__ float g_q[BB * TT * DD];
__device__ float g_k[BB * TT * NKV * DH];
__device__ float g_v[BB * TT * NKV * DH];
__device__ float g_vt[BB * NKV * DH * TT];    // V transposed, tf32-rounded
__device__ float g_ctx[BB * TT * DD];
__device__ float g_xr[BB * TT * DD];          // tf32-rounded copies
__device__ float g_wqr[DD * DD];
__device__ float g_wkr[DD * NKV * DH];
__device__ float g_wvr[DD * NKV * DH];
__device__ float g_wor[DD * DD];
__device__ float2 g_trig[TT * 32];

__device__ __forceinline__ uint32_t f2tf32(float f) {
    uint32_t u;
    asm("cvt.rna.tf32.f32 %0, %1;" : "=r"(u) : "f"(f));
    return u;
}
__device__ __forceinline__ float rtf(float f) {
    return __uint_as_float(f2tf32(f));
}
__device__ __forceinline__ float ex2(float x) {
    float y;
    asm("ex2.approx.f32 %0, %1;" : "=f"(y) : "f"(x));
    return y;
}

__device__ __forceinline__ void mma_tf32(
    float& d0, float& d1, float& d2, float& d3,
    uint32_t a0, uint32_t a1, uint32_t a2, uint32_t a3,
    uint32_t b0, uint32_t b1)
{
    asm volatile(
        "mma.sync.aligned.m16n8k8.row.col.f32.tf32.tf32.f32 "
        "{%0,%1,%2,%3}, {%4,%5,%6,%7}, {%8,%9}, {%0,%1,%2,%3};"
        : "+f"(d0), "+f"(d1), "+f"(d2), "+f"(d3)
        : "r"(a0), "r"(a1), "r"(a2), "r"(a3), "r"(b0), "r"(b1));
}

__device__ __forceinline__ void ldsm4(
    uint32_t& r0, uint32_t& r1, uint32_t& r2, uint32_t& r3, uint32_t saddr)
{
    asm volatile("ldmatrix.sync.aligned.m8n8.x4.shared.b16 {%0,%1,%2,%3}, [%4];"
                 : "=r"(r0), "=r"(r1), "=r"(r2), "=r"(r3) : "r"(saddr));
}

__device__ __forceinline__ void cp16(void* dst, const void* src) {
    uint32_t d = (uint32_t)__cvta_generic_to_shared(dst);
    asm volatile("cp.async.cg.shared.global [%0], [%1], 16;" :: "r"(d), "l"(src));
}
#define CP_COMMIT() asm volatile("cp.async.commit_group;")
#define CP_WAIT0()  asm volatile("cp.async.wait_group 0;" ::: "memory")

// ---------------------------------------------------------------------------
// Merged tf32 round-copy for x + 4 weights (one launch, grid-stride)
// ---------------------------------------------------------------------------
#define N4_X  (BB * TT * DD / 4)
#define N4_WQ (DD * DD / 4)
#define N4_WK (DD * NKV * DH / 4)
__global__ void round_all(
    const float4* __restrict__ x,  const float4* __restrict__ wq,
    const float4* __restrict__ wk, const float4* __restrict__ wv,
    const float4* __restrict__ wo,
    float4* __restrict__ xr,  float4* __restrict__ wqr,
    float4* __restrict__ wkr, float4* __restrict__ wvr,
    float4* __restrict__ wor)
{
    int total = N4_X + 2 * N4_WQ + 2 * N4_WK;
    for (int i = blockIdx.x * blockDim.x + threadIdx.x; i < total;
         i += gridDim.x * blockDim.x) {
        const float4* s;
        float4* d;
        int j = i;
        if (j < N4_X)                 { s = x + j;  d = xr + j; }
        else if ((j -= N4_X) < N4_WQ) { s = wq + j; d = wqr + j; }
        else if ((j -= N4_WQ) < N4_WK){ s = wk + j; d = wkr + j; }
        else if ((j -= N4_WK) < N4_WK){ s = wv + j; d = wvr + j; }
        else { j -= N4_WK;              s = wo + j; d = wor + j; }
        float4 a = *s;
        float4 r;
        r.x = rtf(a.x); r.y = rtf(a.y); r.z = rtf(a.z); r.w = rtf(a.w);
        *d = r;
    }
}

// ---------------------------------------------------------------------------
// TF32 GEMM, cp.async double-buffered, ldmatrix A-fragments (R7 proven).
// ---------------------------------------------------------------------------
#define GBM 128
#define GBN 128
#define GBK 16
#define ASTRIDE 20
#define BSTRIDE 136

__device__ __forceinline__ void gemm_issue(
    const float* __restrict__ A, const float* __restrict__ B,
    int N, int K, int rowBase, int colBase, int k0,
    float (*As)[GBM][ASTRIDE], float (*Bs)[GBK][BSTRIDE], int buf, int tid)
{
#pragma unroll
    for (int i = 0; i < 2; i++) {
        int idx = tid + i * 256;
        int row = idx >> 2;
        int c4 = (idx & 3) * 4;
        cp16(&As[buf][row][c4], A + (size_t)(rowBase + row) * K + k0 + c4);
        int brow = idx >> 5;
        int bc4 = (idx & 31) * 4;
        cp16(&Bs[buf][brow][bc4], B + (size_t)(k0 + brow) * N + colBase + bc4);
    }
}

__device__ __forceinline__ void gemm_body(
    int N, int K,
    const float* __restrict__ A, const float* __restrict__ B,
    float* __restrict__ C, int rowBase, int colBase,
    float (*As)[GBM][ASTRIDE], float (*Bs)[GBK][BSTRIDE])
{
    const int tid = threadIdx.x;
    const int lane = tid & 31;
    const int warp = tid >> 5;
    const int g = lane >> 2;
    const int t = lane & 3;
    const int warpRow = warp & 1;
    const int warpCol = warp >> 1;
    const int lm = lane >> 3;
    const int lr = lane & 7;

    const uint32_t aLaneOff = (uint32_t)((((lm & 1) * 8 + lr) * ASTRIDE + (lm >> 1) * 4) * 4);

    gemm_issue(A, B, N, K, rowBase, colBase, 0, As, Bs, 0, tid);
    CP_COMMIT();

    float acc[4][4][4];
#pragma unroll
    for (int mi = 0; mi < 4; mi++)
#pragma unroll
        for (int ni = 0; ni < 4; ni++)
#pragma unroll
            for (int r = 0; r < 4; r++) acc[mi][ni][r] = 0.f;

    const int nIter = K / GBK;
    int cur = 0;
    for (int it = 0; it < nIter; it++) {
        CP_WAIT0();
        __syncthreads();
        if (it + 1 < nIter) {
            gemm_issue(A, B, N, K, rowBase, colBase, (it + 1) * GBK,
                       As, Bs, cur ^ 1, tid);
            CP_COMMIT();
        }

        uint32_t as_base = (uint32_t)__cvta_generic_to_shared(&As[cur][0][0]);

#pragma unroll
        for (int ks = 0; ks < GBK; ks += 8) {
            uint32_t af[4][4];
            uint32_t bf[4][2];
#pragma unroll
            for (int mi = 0; mi < 4; mi++) {
                int rb = warpRow * 64 + mi * 16;
                ldsm4(af[mi][0], af[mi][1], af[mi][2], af[mi][3],
                      as_base + (uint32_t)((rb * ASTRIDE + ks) * 4) + aLaneOff);
            }
#pragma unroll
            for (int ni = 0; ni < 4; ni++) {
                int cb = warpCol * 32 + ni * 8 + g;
                bf[ni][0] = __float_as_uint(Bs[cur][ks + t][cb]);
                bf[ni][1] = __float_as_uint(Bs[cur][ks + t + 4][cb]);
            }
#pragma unroll
            for (int mi = 0; mi < 4; mi++)
#pragma unroll
                for (int ni = 0; ni < 4; ni++)
                    mma_tf32(acc[mi][ni][0], acc[mi][ni][1],
                             acc[mi][ni][2], acc[mi][ni][3],
                             af[mi][0], af[mi][1], af[mi][2], af[mi][3],
                             bf[ni][0], bf[ni][1]);
        }
        cur ^= 1;
    }

#pragma unroll
    for (int mi = 0; mi < 4; mi++) {
#pragma unroll
        for (int ni = 0; ni < 4; ni++) {
            int r0 = rowBase + warpRow * 64 + mi * 16 + g;
            int col = colBase + warpCol * 32 + ni * 8 + 2 * t;
            *(float2*)(C + (size_t)r0 * N + col) =
                make_float2(acc[mi][ni][0], acc[mi][ni][1]);
            *(float2*)(C + (size_t)(r0 + 8) * N + col) =
                make_float2(acc[mi][ni][2], acc[mi][ni][3]);
        }
    }
}

__global__ __launch_bounds__(256, 2) void gemm_tf32(
    int M, int N, int K,
    const float* __restrict__ A, const float* __restrict__ B,
    float* __restrict__ C)
{
    __shared__ float As[2][GBM][ASTRIDE];
    __shared__ float Bs[2][GBK][BSTRIDE];
    gemm_body(N, K, A, B, C, blockIdx.y * GBM, blockIdx.x * GBN, As, Bs);
}

__global__ __launch_bounds__(256, 2) void gemm_qkv(
    const float* __restrict__ X,
    const float* __restrict__ Wq, const float* __restrict__ Wk,
    const float* __restrict__ Wv,
    float* __restrict__ Qo, float* __restrict__ Ko, float* __restrict__ Vo)
{
    __shared__ float As[2][GBM][ASTRIDE];
    __shared__ float Bs[2][GBK][BSTRIDE];

    int bx = blockIdx.x;
    const float* B;
    float* C;
    int N, colBase;
    if (bx < 16)      { B = Wq; C = Qo; N = DD;        colBase = bx * 128; }
    else if (bx < 20) { B = Wk; C = Ko; N = NKV * DH;  colBase = (bx - 16) * 128; }
    else              { B = Wv; C = Vo; N = NKV * DH;  colBase = (bx - 20) * 128; }

    gemm_body(N, DD, X, B, C, blockIdx.y * GBM, colBase, As, Bs);
}

// ---------------------------------------------------------------------------
// Trig table init
// ---------------------------------------------------------------------------
__global__ void trig_init()
{
    int idx = blockIdx.x * blockDim.x + threadIdx.x;
    if (idx >= TT * 32) return;
    int t = idx >> 5;
    int i = idx & 31;
    double inv = exp(-(double)i * (9.210340371976184 / 32.0));
    float ang = (float)t * (float)inv;
    float c, s;
    sincosf(ang, &s, &c);
    g_trig[idx] = make_float2(c, s);
}

// ---------------------------------------------------------------------------
// RoPE (q, k) + V transpose (v -> vt, tf32-rounded). One launch.
// ---------------------------------------------------------------------------
__device__ __forceinline__ void rope_apply(float* __restrict__ X, int nheads, int idx)
{
    int i4 = (idx & 7) * 4;
    int hn = idx >> 3;
    int h = hn % nheads;
    int n = hn / nheads;
    int t = n & (TT - 1);

    const float2* tr = g_trig + t * 32 + i4;
    float2 t0 = tr[0], t1 = tr[1], t2 = tr[2], t3 = tr[3];

    float* p = X + (size_t)n * nheads * 64 + h * 64 + i4;
    float4 x1 = *(float4*)p;
    float4 x2 = *(float4*)(p + 32);

    float4 y1, y2;
    y1.x = rtf(x1.x * t0.x - x2.x * t0.y);  y2.x = rtf(x2.x * t0.x + x1.x * t0.y);
    y1.y = rtf(x1.y * t1.x - x2.y * t1.y);  y2.y = rtf(x2.y * t1.x + x1.y * t1.y);
    y1.z = rtf(x1.z * t2.x - x2.z * t2.y);  y2.z = rtf(x2.z * t2.x + x1.z * t2.y);
    y1.w = rtf(x1.w * t3.x - x2.w * t3.y);  y2.w = rtf(x2.w * t3.x + x1.w * t3.y);
    *(float4*)p = y1;
    *(float4*)(p + 32) = y2;
}

__global__ void rope_round(float* __restrict__ Qx, float* __restrict__ Kx,
                           const float* __restrict__ Vx, float* __restrict__ VT,
                           int totq, int totk, int totv)
{
    int idx = blockIdx.x * blockDim.x + threadIdx.x;
    if (idx < totq) {
        rope_apply(Qx, NH, idx);
    } else if (idx < totq + totk) {
        rope_apply(Kx, NKV, idx - totq);
    } else if (idx < totq + totk + totv) {
        int i = idx - totq - totk;
        int t = i & (TT - 1);
        int r = i >> 11;
        int d4 = r & 15;
        int kb = r >> 4;           // b*NKV + kh
        const float* src = Vx + ((size_t)((kb >> 3) * TT + t) * (NKV * DH))
                              + (kb & 7) * DH + d4 * 4;
        float4 a = *(const float4*)src;
        float* dst = VT + ((size_t)kb * DH + d4 * 4) * TT + t;
        dst[0 * TT] = rtf(a.x);
        dst[1 * TT] = rtf(a.y);
        dst[2 * TT] = rtf(a.z);
        dst[3 * TT] = rtf(a.w);
    }
}

// ---------------------------------------------------------------------------
// Tensor-core flash attention (causal, GQA), cp.async double-buffered,
// ldmatrix fragments, shuffle PV relayout (R7 proven), base-2 softmax.
// ---------------------------------------------------------------------------
#define KV_BUF_FLOATS 8704   // 2 * 64*68
#define KS_OFF 0
#define VS_OFF 4352
#define KSTRIDE 68

__device__ __forceinline__ void attn_issue_kv(
    const float* __restrict__ K, const float* __restrict__ VT,
    float* sm, int buf, int b, int kh, int s0, int tid)
{
    size_t vtrow = ((size_t)(b * NKV + kh)) * DH;
#pragma unroll
    for (int i = 0; i < 4; i++) {
        int lin = tid + i * 256;
        int r = lin >> 4;
        int c4 = (lin & 15) * 4;
        cp16(sm + buf * KV_BUF_FLOATS + KS_OFF + r * KSTRIDE + c4,
             K + (size_t)(b * TT + s0 + r) * (NKV * DH) + kh * DH + c4);
        cp16(sm + buf * KV_BUF_FLOATS + VS_OFF + r * KSTRIDE + c4,
             VT + (vtrow + r) * TT + s0 + c4);
    }
}

__global__ __launch_bounds__(256) void flash_attn_tc(
    const float* __restrict__ Q, const float* __restrict__ K,
    const float* __restrict__ VT, float* __restrict__ O)
{
    extern __shared__ float sm[];

    const int tid = threadIdx.x;
    const int lane = tid & 31;
    const int warp = tid >> 5;
    const int g = lane >> 2;
    const int t = lane & 3;
    const int lm = lane >> 3;
    const int lr = lane & 7;
    const int qt = blockIdx.x;
    const int h  = blockIdx.y;
    const int b  = blockIdx.z;
    const int kh = h / GG;
    const int rowBase = qt * 128 + warp * 16;
    const int kend = (qt + 1) * 128;

    // scale folds 1/sqrt(64) and log2(e): softmax in base-2 domain
    const float qscale = 0.125f * 1.44269504088896f;

    // ---- stage Q through buffer-0 VT region, extract A fragments ----
    uint32_t qa[8][4];
    {
        float (*Qs)[KSTRIDE] = (float(*)[KSTRIDE])(sm + VS_OFF);
#pragma unroll
        for (int half = 0; half < 2; half++) {
#pragma unroll
            for (int i = 0; i < 4; i++) {
                int lin = tid + i * 256;
                int r = lin >> 4;
                int c4 = (lin & 15) * 4;
                const float* src = Q + (size_t)(b * TT + qt * 128 + half * 64 + r) * DD
                                     + h * DH + c4;
                *(float4*)&Qs[r][c4] = *(const float4*)src;
            }
            __syncthreads();
            if ((warp >> 2) == half) {
                int qlr = (warp & 3) * 16 + g;
#pragma unroll
                for (int kc = 0; kc < 8; kc++) {
                    qa[kc][0] = f2tf32(Qs[qlr][kc * 8 + t] * qscale);
                    qa[kc][1] = f2tf32(Qs[qlr + 8][kc * 8 + t] * qscale);
                    qa[kc][2] = f2tf32(Qs[qlr][kc * 8 + t + 4] * qscale);
                    qa[kc][3] = f2tf32(Qs[qlr + 8][kc * 8 + t + 4] * qscale);
                }
            }
            __syncthreads();
        }
    }

    attn_issue_kv(K, VT, sm, 0, b, kh, 0, tid);
    CP_COMMIT();

    float oacc[8][4];
#pragma unroll
    for (int ni = 0; ni < 8; ni++)
#pragma unroll
        for (int r = 0; r < 4; r++) oacc[ni][r] = 0.f;
    float m0 = -1e30f, m1 = -1e30f, l0 = 0.f, l1 = 0.f;

    const int srcA = (lane & 28) | (t >> 1);
    const bool odd = (t & 1);

    const uint32_t kLaneOff = (uint32_t)((lr * KSTRIDE + (lm >> 1) * 8 + (lm & 1) * 4) * 4);
    const uint32_t vLaneOff = (uint32_t)((((lm >> 1) * 8 + lr) * KSTRIDE + (lm & 1) * 4) * 4);

    int cur = 0;
    for (int s0 = 0; s0 < kend; s0 += 64) {
        CP_WAIT0();
        __syncthreads();
        if (s0 + 64 < kend) {
            attn_issue_kv(K, VT, sm, cur ^ 1, b, kh, s0 + 64, tid);
            CP_COMMIT();
        }

        if (s0 <= rowBase + 15) {
            uint32_t ks_base = (uint32_t)__cvta_generic_to_shared(
                sm + cur * KV_BUF_FLOATS + KS_OFF);
            uint32_t vs_base = (uint32_t)__cvta_generic_to_shared(
                sm + cur * KV_BUF_FLOATS + VS_OFF);

            // ---- S' = (Q*scale*log2e) @ K^T ----
            float sacc[8][4];
#pragma unroll
            for (int ni = 0; ni < 8; ni++) {
                sacc[ni][0] = 0.f; sacc[ni][1] = 0.f;
                sacc[ni][2] = 0.f; sacc[ni][3] = 0.f;
#pragma unroll
                for (int j = 0; j < 4; j++) {
                    uint32_t b0a, b1a, b0b, b1b;
                    ldsm4(b0a, b1a, b0b, b1b,
                          ks_base + (uint32_t)((ni * 8 * KSTRIDE + j * 16) * 4) + kLaneOff);
                    mma_tf32(sacc[ni][0], sacc[ni][1], sacc[ni][2], sacc[ni][3],
                             qa[2*j][0], qa[2*j][1], qa[2*j][2], qa[2*j][3], b0a, b1a);
                    mma_tf32(sacc[ni][0], sacc[ni][1], sacc[ni][2], sacc[ni][3],
                             qa[2*j+1][0], qa[2*j+1][1], qa[2*j+1][2], qa[2*j+1][3], b0b, b1b);
                }
            }

            // ---- causal mask ----
            if (s0 + 63 > rowBase) {
                int r0 = rowBase + g;
                int r1 = r0 + 8;
#pragma unroll
                for (int ni = 0; ni < 8; ni++) {
                    int c = s0 + ni * 8 + 2 * t;
                    if (c > r0)     sacc[ni][0] = -1e30f;
                    if (c + 1 > r0) sacc[ni][1] = -1e30f;
                    if (c > r1)     sacc[ni][2] = -1e30f;
                    if (c + 1 > r1) sacc[ni][3] = -1e30f;
                }
            }

            // ---- online softmax (base 2) ----
            float mx0 = -1e30f, mx1 = -1e30f;
#pragma unroll
            for (int ni = 0; ni < 8; ni++) {
                mx0 = fmaxf(mx0, fmaxf(sacc[ni][0], sacc[ni][1]));
                mx1 = fmaxf(mx1, fmaxf(sacc[ni][2], sacc[ni][3]));
            }
            mx0 = fmaxf(mx0, __shfl_xor_sync(0xffffffffu, mx0, 1));
            mx0 = fmaxf(mx0, __shfl_xor_sync(0xffffffffu, mx0, 2));
            mx1 = fmaxf(mx1, __shfl_xor_sync(0xffffffffu, mx1, 1));
            mx1 = fmaxf(mx1, __shfl_xor_sync(0xffffffffu, mx1, 2));

            float mn0 = fmaxf(m0, mx0), mn1 = fmaxf(m1, mx1);
            float cr0 = ex2(m0 - mn0), cr1 = ex2(m1 - mn1);
            m0 = mn0; m1 = mn1;
            l0 *= cr0; l1 *= cr1;
#pragma unroll
            for (int ni = 0; ni < 8; ni++) {
                oacc[ni][0] *= cr0; oacc[ni][1] *= cr0;
                oacc[ni][2] *= cr1; oacc[ni][3] *= cr1;
            }
#pragma unroll
            for (int ni = 0; ni < 8; ni++) {
                sacc[ni][0] = ex2(sacc[ni][0] - m0);
                sacc[ni][1] = ex2(sacc[ni][1] - m0);
                sacc[ni][2] = ex2(sacc[ni][2] - m1);
                sacc[ni][3] = ex2(sacc[ni][3] - m1);
                l0 += sacc[ni][0] + sacc[ni][1];
                l1 += sacc[ni][2] + sacc[ni][3];
            }

            // ---- O += P @ V (shuffle relayout C-frag -> A-frag) ----
#pragma unroll
            for (int kc = 0; kc < 8; kc++) {
                float v00 = __shfl_sync(0xffffffffu, sacc[kc][0], srcA);
                float v01 = __shfl_sync(0xffffffffu, sacc[kc][1], srcA);
                float v10 = __shfl_sync(0xffffffffu, sacc[kc][2], srcA);
                float v11 = __shfl_sync(0xffffffffu, sacc[kc][3], srcA);
                float w00 = __shfl_sync(0xffffffffu, sacc[kc][0], srcA + 2);
                float w01 = __shfl_sync(0xffffffffu, sacc[kc][1], srcA + 2);
                float w10 = __shfl_sync(0xffffffffu, sacc[kc][2], srcA + 2);
                float w11 = __shfl_sync(0xffffffffu, sacc[kc][3], srcA + 2);
                uint32_t a0 = f2tf32(odd ? v01 : v00);
                uint32_t a1 = f2tf32(odd ? v11 : v10);
                uint32_t a2 = f2tf32(odd ? w01 : w00);
                uint32_t a3 = f2tf32(odd ? w11 : w10);
#pragma unroll
                for (int jj = 0; jj < 4; jj++) {
                    uint32_t c0, c1, c2, c3;
                    ldsm4(c0, c1, c2, c3,
                          vs_base + (uint32_t)((jj * 16 * KSTRIDE + kc * 8) * 4) + vLaneOff);
                    mma_tf32(oacc[2*jj][0], oacc[2*jj][1], oacc[2*jj][2], oacc[2*jj][3],
                             a0, a1, a2, a3, c0, c1);
                    mma_tf32(oacc[2*jj+1][0], oacc[2*jj+1][1], oacc[2*jj+1][2], oacc[2*jj+1][3],
                             a0, a1, a2, a3, c2, c3);
                }
            }
        }
        cur ^= 1;
    }

    l0 += __shfl_xor_sync(0xffffffffu, l0, 1);
    l0 += __shfl_xor_sync(0xffffffffu, l0, 2);
    l1 += __shfl_xor_sync(0xffffffffu, l1, 1);
    l1 += __shfl_xor_sync(0xffffffffu, l1, 2);
    float inv0 = 1.f / l0, inv1 = 1.f / l1;

    int R0 = rowBase + g;
    float* o0 = O + (size_t)(b * TT + R0) * DD + h * DH;
    float* o1 = o0 + (size_t)8 * DD;
#pragma unroll
    for (int ni = 0; ni < 8; ni++) {
        *(float2*)(o0 + ni * 8 + 2 * t) =
            make_float2(rtf(oacc[ni][0] * inv0), rtf(oacc[ni][1] * inv0));
        *(float2*)(o1 + ni * 8 + 2 * t) =
            make_float2(rtf(oacc[ni][2] * inv1), rtf(oacc[ni][3] * inv1));
    }
}

// ---------------------------------------------------------------------------
// Launch
// ---------------------------------------------------------------------------
extern "C" void kernel_launch(void* const* d_in, const int* in_sizes, int n_in,
                              void* d_out, int out_size)
{
    const float* x  = (const float*)d_in[0];
    const float* Wq = (const float*)d_in[1];
    const float* Wk = (const float*)d_in[2];
    const float* Wv = (const float*)d_in[3];
    const float* Wo = (const float*)d_in[4];
    float* out = (float*)d_out;

    float *q, *k, *v, *vt, *ctx, *xr, *wqr, *wkr, *wvr, *wor;
    cudaGetSymbolAddress((void**)&q,   g_q);
    cudaGetSymbolAddress((void**)&k,   g_k);
    cudaGetSymbolAddress((void**)&v,   g_v);
    cudaGetSymbolAddress((void**)&vt,  g_vt);
    cudaGetSymbolAddress((void**)&ctx, g_ctx);
    cudaGetSymbolAddress((void**)&xr,  g_xr);
    cudaGetSymbolAddress((void**)&wqr, g_wqr);
    cudaGetSymbolAddress((void**)&wkr, g_wkr);
    cudaGetSymbolAddress((void**)&wvr, g_wvr);
    cudaGetSymbolAddress((void**)&wor, g_wor);

    static bool attr_set = false;
    if (!attr_set) {
        cudaFuncSetAttribute(flash_attn_tc,
                             cudaFuncAttributeMaxDynamicSharedMemorySize,
                             2 * KV_BUF_FLOATS * (int)sizeof(float));
        attr_set = true;
    }

    const int M = BB * TT;   // 4096

    trig_init<<<(TT * 32 + 255) / 256, 256>>>();

    // merged tf32 round-copy of all inputs (one launch)
    round_all<<<1184, 256>>>((const float4*)x,  (const float4*)Wq,
                             (const float4*)Wk, (const float4*)Wv,
                             (const float4*)Wo,
                             (float4*)xr,  (float4*)wqr,
                             (float4*)wkr, (float4*)wvr, (float4*)wor);

    // Fused QKV projection
    gemm_qkv<<<dim3(24, M / GBM), 256>>>(xr, wqr, wkr, wvr, q, k, v);

    // RoPE (q, k) + V transpose/round
    {
        int totq = M * NH * 8;
        int totk = M * NKV * 8;
        int totv = M * NKV * 16;
        rope_round<<<(totq + totk + totv + 255) / 256, 256>>>(q, k, v, vt,
                                                              totq, totk, totv);
    }

    // Attention
    flash_attn_tc<<<dim3(TT / 128, NH, BB), 256,
                    2 * KV_BUF_FLOATS * sizeof(float)>>>(q, k, vt, ctx);

    // Output projection
    gemm_tf32<<<dim3(DD / GBN, M / GBM), 256>>>(M, DD, DD, ctx, wor, out);
}

// round 15
// speedup vs baseline: 1.5257x; 1.5257x over previous
#include <cuda_runtime.h>
#include <math.h>
#include <stdint.h>

// Problem constants
#define BB 2
#define TT 2048
#define DD 2048
#define NH 32
#define NKV 8
#define DH 64
#define GG 4   // NH / NKV

// Scratch (device globals)
__device__ float g_q[BB * TT * DD];
__device__ float g_k[BB * TT * NKV * DH];
__device__ float g_v[BB * TT * NKV * DH];
__device__ float g_vt[BB * NKV * DH * TT];    // V transposed, tf32-rounded
__device__ float g_ctx[BB * TT * DD];
__device__ float g_xr[BB * TT * DD];          // tf32-rounded copies
__device__ float g_wqr[DD * DD];
__device__ float g_wkr[DD * NKV * DH];
__device__ float g_wvr[DD * NKV * DH];
__device__ float g_wor[DD * DD];
__device__ float2 g_trig[TT * 32];

__device__ __forceinline__ uint32_t f2tf32(float f) {
    uint32_t u;
    asm("cvt.rna.tf32.f32 %0, %1;" : "=r"(u) : "f"(f));
    return u;
}
__device__ __forceinline__ float rtf(float f) {
    return __uint_as_float(f2tf32(f));
}
__device__ __forceinline__ float ex2(float x) {
    float y;
    asm("ex2.approx.f32 %0, %1;" : "=f"(y) : "f"(x));
    return y;
}

__device__ __forceinline__ void mma_tf32(
    float& d0, float& d1, float& d2, float& d3,
    uint32_t a0, uint32_t a1, uint32_t a2, uint32_t a3,
    uint32_t b0, uint32_t b1)
{
    asm volatile(
        "mma.sync.aligned.m16n8k8.row.col.f32.tf32.tf32.f32 "
        "{%0,%1,%2,%3}, {%4,%5,%6,%7}, {%8,%9}, {%0,%1,%2,%3};"
        : "+f"(d0), "+f"(d1), "+f"(d2), "+f"(d3)
        : "r"(a0), "r"(a1), "r"(a2), "r"(a3), "r"(b0), "r"(b1));
}

__device__ __forceinline__ void ldsm4(
    uint32_t& r0, uint32_t& r1, uint32_t& r2, uint32_t& r3, uint32_t saddr)
{
    asm volatile("ldmatrix.sync.aligned.m8n8.x4.shared.b16 {%0,%1,%2,%3}, [%4];"
                 : "=r"(r0), "=r"(r1), "=r"(r2), "=r"(r3) : "r"(saddr));
}

__device__ __forceinline__ void cp16(void* dst, const void* src) {
    uint32_t d = (uint32_t)__cvta_generic_to_shared(dst);
    asm volatile("cp.async.cg.shared.global [%0], [%1], 16;" :: "r"(d), "l"(src));
}
#define CP_COMMIT() asm volatile("cp.async.commit_group;")
#define CP_WAIT0()  asm volatile("cp.async.wait_group 0;" ::: "memory")

// ---------------------------------------------------------------------------
// Merged tf32 round-copy for x + 4 weights (one launch, grid-stride)
// ---------------------------------------------------------------------------
#define N4_X  (BB * TT * DD / 4)
#define N4_WQ (DD * DD / 4)
#define N4_WK (DD * NKV * DH / 4)
__global__ void round_all(
    const float4* __restrict__ x,  const float4* __restrict__ wq,
    const float4* __restrict__ wk, const float4* __restrict__ wv,
    const float4* __restrict__ wo,
    float4* __restrict__ xr,  float4* __restrict__ wqr,
    float4* __restrict__ wkr, float4* __restrict__ wvr,
    float4* __restrict__ wor)
{
    int total = N4_X + 2 * N4_WQ + 2 * N4_WK;
    for (int i = blockIdx.x * blockDim.x + threadIdx.x; i < total;
         i += gridDim.x * blockDim.x) {
        const float4* s;
        float4* d;
        int j = i;
        if (j < N4_X)                 { s = x + j;  d = xr + j; }
        else if ((j -= N4_X) < N4_WQ) { s = wq + j; d = wqr + j; }
        else if ((j -= N4_WQ) < N4_WK){ s = wk + j; d = wkr + j; }
        else if ((j -= N4_WK) < N4_WK){ s = wv + j; d = wvr + j; }
        else { j -= N4_WK;              s = wo + j; d = wor + j; }
        float4 a = *s;
        float4 r;
        r.x = rtf(a.x); r.y = rtf(a.y); r.z = rtf(a.z); r.w = rtf(a.w);
        *d = r;
    }
}

// ---------------------------------------------------------------------------
// TF32 GEMM, cp.async double-buffered, ldmatrix A-fragments (R7 proven).
// ---------------------------------------------------------------------------
#define GBM 128
#define GBN 128
#define GBK 16
#define ASTRIDE 20
#define BSTRIDE 136

__device__ __forceinline__ void gemm_issue(
    const float* __restrict__ A, const float* __restrict__ B,
    int N, int K, int rowBase, int colBase, int k0,
    float (*As)[GBM][ASTRIDE], float (*Bs)[GBK][BSTRIDE], int buf, int tid)
{
#pragma unroll
    for (int i = 0; i < 2; i++) {
        int idx = tid + i * 256;
        int row = idx >> 2;
        int c4 = (idx & 3) * 4;
        cp16(&As[buf][row][c4], A + (size_t)(rowBase + row) * K + k0 + c4);
        int brow = idx >> 5;
        int bc4 = (idx & 31) * 4;
        cp16(&Bs[buf][brow][bc4], B + (size_t)(k0 + brow) * N + colBase + bc4);
    }
}

__device__ __forceinline__ void gemm_body(
    int N, int K,
    const float* __restrict__ A, const float* __restrict__ B,
    float* __restrict__ C, int rowBase, int colBase,
    float (*As)[GBM][ASTRIDE], float (*Bs)[GBK][BSTRIDE])
{
    const int tid = threadIdx.x;
    const int lane = tid & 31;
    const int warp = tid >> 5;
    const int g = lane >> 2;
    const int t = lane & 3;
    const int warpRow = warp & 1;
    const int warpCol = warp >> 1;
    const int lm = lane >> 3;
    const int lr = lane & 7;

    const uint32_t aLaneOff = (uint32_t)((((lm & 1) * 8 + lr) * ASTRIDE + (lm >> 1) * 4) * 4);

    gemm_issue(A, B, N, K, rowBase, colBase, 0, As, Bs, 0, tid);
    CP_COMMIT();

    float acc[4][4][4];
#pragma unroll
    for (int mi = 0; mi < 4; mi++)
#pragma unroll
        for (int ni = 0; ni < 4; ni++)
#pragma unroll
            for (int r = 0; r < 4; r++) acc[mi][ni][r] = 0.f;

    const int nIter = K / GBK;
    int cur = 0;
    for (int it = 0; it < nIter; it++) {
        CP_WAIT0();
        __syncthreads();
        if (it + 1 < nIter) {
            gemm_issue(A, B, N, K, rowBase, colBase, (it + 1) * GBK,
                       As, Bs, cur ^ 1, tid);
            CP_COMMIT();
        }

        uint32_t as_base = (uint32_t)__cvta_generic_to_shared(&As[cur][0][0]);

#pragma unroll
        for (int ks = 0; ks < GBK; ks += 8) {
            uint32_t af[4][4];
            uint32_t bf[4][2];
#pragma unroll
            for (int mi = 0; mi < 4; mi++) {
                int rb = warpRow * 64 + mi * 16;
                ldsm4(af[mi][0], af[mi][1], af[mi][2], af[mi][3],
                      as_base + (uint32_t)((rb * ASTRIDE + ks) * 4) + aLaneOff);
            }
#pragma unroll
            for (int ni = 0; ni < 4; ni++) {
                int cb = warpCol * 32 + ni * 8 + g;
                bf[ni][0] = __float_as_uint(Bs[cur][ks + t][cb]);
                bf[ni][1] = __float_as_uint(Bs[cur][ks + t + 4][cb]);
            }
#pragma unroll
            for (int mi = 0; mi < 4; mi++)
#pragma unroll
                for (int ni = 0; ni < 4; ni++)
                    mma_tf32(acc[mi][ni][0], acc[mi][ni][1],
                             acc[mi][ni][2], acc[mi][ni][3],
                             af[mi][0], af[mi][1], af[mi][2], af[mi][3],
                             bf[ni][0], bf[ni][1]);
        }
        cur ^= 1;
    }

#pragma unroll
    for (int mi = 0; mi < 4; mi++) {
#pragma unroll
        for (int ni = 0; ni < 4; ni++) {
            int r0 = rowBase + warpRow * 64 + mi * 16 + g;
            int col = colBase + warpCol * 32 + ni * 8 + 2 * t;
            *(float2*)(C + (size_t)r0 * N + col) =
                make_float2(acc[mi][ni][0], acc[mi][ni][1]);
            *(float2*)(C + (size_t)(r0 + 8) * N + col) =
                make_float2(acc[mi][ni][2], acc[mi][ni][3]);
        }
    }
}

__global__ __launch_bounds__(256, 2) void gemm_tf32(
    int M, int N, int K,
    const float* __restrict__ A, const float* __restrict__ B,
    float* __restrict__ C)
{
    __shared__ float As[2][GBM][ASTRIDE];
    __shared__ float Bs[2][GBK][BSTRIDE];
    gemm_body(N, K, A, B, C, blockIdx.y * GBM, blockIdx.x * GBN, As, Bs);
}

__global__ __launch_bounds__(256, 2) void gemm_qkv(
    const float* __restrict__ X,
    const float* __restrict__ Wq, const float* __restrict__ Wk,
    const float* __restrict__ Wv,
    float* __restrict__ Qo, float* __restrict__ Ko, float* __restrict__ Vo)
{
    __shared__ float As[2][GBM][ASTRIDE];
    __shared__ float Bs[2][GBK][BSTRIDE];

    int bx = blockIdx.x;
    const float* B;
    float* C;
    int N, colBase;
    if (bx < 16)      { B = Wq; C = Qo; N = DD;        colBase = bx * 128; }
    else if (bx < 20) { B = Wk; C = Ko; N = NKV * DH;  colBase = (bx - 16) * 128; }
    else              { B = Wv; C = Vo; N = NKV * DH;  colBase = (bx - 20) * 128; }

    gemm_body(N, DD, X, B, C, blockIdx.y * GBM, colBase, As, Bs);
}

// ---------------------------------------------------------------------------
// Trig table init
// ---------------------------------------------------------------------------
__global__ void trig_init()
{
    int idx = blockIdx.x * blockDim.x + threadIdx.x;
    if (idx >= TT * 32) return;
    int t = idx >> 5;
    int i = idx & 31;
    double inv = exp(-(double)i * (9.210340371976184 / 32.0));
    float ang = (float)t * (float)inv;
    float c, s;
    sincosf(ang, &s, &c);
    g_trig[idx] = make_float2(c, s);
}

// ---------------------------------------------------------------------------
// RoPE (q, k) + V transpose (v -> vt, tf32-rounded). One launch.
// ---------------------------------------------------------------------------
__device__ __forceinline__ void rope_apply(float* __restrict__ X, int nheads, int idx)
{
    int i4 = (idx & 7) * 4;
    int hn = idx >> 3;
    int h = hn % nheads;
    int n = hn / nheads;
    int t = n & (TT - 1);

    const float2* tr = g_trig + t * 32 + i4;
    float2 t0 = tr[0], t1 = tr[1], t2 = tr[2], t3 = tr[3];

    float* p = X + (size_t)n * nheads * 64 + h * 64 + i4;
    float4 x1 = *(float4*)p;
    float4 x2 = *(float4*)(p + 32);

    float4 y1, y2;
    y1.x = rtf(x1.x * t0.x - x2.x * t0.y);  y2.x = rtf(x2.x * t0.x + x1.x * t0.y);
    y1.y = rtf(x1.y * t1.x - x2.y * t1.y);  y2.y = rtf(x2.y * t1.x + x1.y * t1.y);
    y1.z = rtf(x1.z * t2.x - x2.z * t2.y);  y2.z = rtf(x2.z * t2.x + x1.z * t2.y);
    y1.w = rtf(x1.w * t3.x - x2.w * t3.y);  y2.w = rtf(x2.w * t3.x + x1.w * t3.y);
    *(float4*)p = y1;
    *(float4*)(p + 32) = y2;
}

__global__ void rope_round(float* __restrict__ Qx, float* __restrict__ Kx,
                           const float* __restrict__ Vx, float* __restrict__ VT,
                           int totq, int totk, int totv)
{
    int idx = blockIdx.x * blockDim.x + threadIdx.x;
    if (idx < totq) {
        rope_apply(Qx, NH, idx);
    } else if (idx < totq + totk) {
        rope_apply(Kx, NKV, idx - totq);
    } else if (idx < totq + totk + totv) {
        int i = idx - totq - totk;
        int t = i & (TT - 1);
        int r = i >> 11;
        int d4 = r & 15;
        int kb = r >> 4;           // b*NKV + kh
        const float* src = Vx + ((size_t)((kb >> 3) * TT + t) * (NKV * DH))
                              + (kb & 7) * DH + d4 * 4;
        float4 a = *(const float4*)src;
        float* dst = VT + ((size_t)kb * DH + d4 * 4) * TT + t;
        dst[0 * TT] = rtf(a.x);
        dst[1 * TT] = rtf(a.y);
        dst[2 * TT] = rtf(a.z);
        dst[3 * TT] = rtf(a.w);
    }
}

// ---------------------------------------------------------------------------
// Tensor-core flash attention (causal, GQA), cp.async double-buffered,
// ldmatrix fragments, shuffle PV relayout (R7 proven), base-2 softmax.
// ---------------------------------------------------------------------------
#define KV_BUF_FLOATS 8704   // 2 * 64*68
#define KS_OFF 0
#define VS_OFF 4352
#define KSTRIDE 68

__device__ __forceinline__ void attn_issue_kv(
    const float* __restrict__ K, const float* __restrict__ VT,
    float* sm, int buf, int b, int kh, int s0, int tid)
{
    size_t vtrow = ((size_t)(b * NKV + kh)) * DH;
#pragma unroll
    for (int i = 0; i < 4; i++) {
        int lin = tid + i * 256;
        int r = lin >> 4;
        int c4 = (lin & 15) * 4;
        cp16(sm + buf * KV_BUF_FLOATS + KS_OFF + r * KSTRIDE + c4,
             K + (size_t)(b * TT + s0 + r) * (NKV * DH) + kh * DH + c4);
        cp16(sm + buf * KV_BUF_FLOATS + VS_OFF + r * KSTRIDE + c4,
             VT + (vtrow + r) * TT + s0 + c4);
    }
}

__global__ __launch_bounds__(256) void flash_attn_tc(
    const float* __restrict__ Q, const float* __restrict__ K,
    const float* __restrict__ VT, float* __restrict__ O)
{
    extern __shared__ float sm[];

    const int tid = threadIdx.x;
    const int lane = tid & 31;
    const int warp = tid >> 5;
    const int g = lane >> 2;
    const int t = lane & 3;
    const int lm = lane >> 3;
    const int lr = lane & 7;
    const int qt = blockIdx.x;
    const int h  = blockIdx.y;
    const int b  = blockIdx.z;
    const int kh = h / GG;
    const int rowBase = qt * 128 + warp * 16;
    const int kend = (qt + 1) * 128;

    // scale folds 1/sqrt(64) and log2(e): softmax in base-2 domain
    const float qscale = 0.125f * 1.44269504088896f;

    // ---- stage Q through buffer-0 VT region, extract A fragments ----
    uint32_t qa[8][4];
    {
        float (*Qs)[KSTRIDE] = (float(*)[KSTRIDE])(sm + VS_OFF);
#pragma unroll
        for (int half = 0; half < 2; half++) {
#pragma unroll
            for (int i = 0; i < 4; i++) {
                int lin = tid + i * 256;
                int r = lin >> 4;
                int c4 = (lin & 15) * 4;
                const float* src = Q + (size_t)(b * TT + qt * 128 + half * 64 + r) * DD
                                     + h * DH + c4;
                *(float4*)&Qs[r][c4] = *(const float4*)src;
            }
            __syncthreads();
            if ((warp >> 2) == half) {
                int qlr = (warp & 3) * 16 + g;
#pragma unroll
                for (int kc = 0; kc < 8; kc++) {
                    qa[kc][0] = f2tf32(Qs[qlr][kc * 8 + t] * qscale);
                    qa[kc][1] = f2tf32(Qs[qlr + 8][kc * 8 + t] * qscale);
                    qa[kc][2] = f2tf32(Qs[qlr][kc * 8 + t + 4] * qscale);
                    qa[kc][3] = f2tf32(Qs[qlr + 8][kc * 8 + t + 4] * qscale);
                }
            }
            __syncthreads();
        }
    }

    attn_issue_kv(K, VT, sm, 0, b, kh, 0, tid);
    CP_COMMIT();

    float oacc[8][4];
#pragma unroll
    for (int ni = 0; ni < 8; ni++)
#pragma unroll
        for (int r = 0; r < 4; r++) oacc[ni][r] = 0.f;
    float m0 = -1e30f, m1 = -1e30f, l0 = 0.f, l1 = 0.f;

    const int srcA = (lane & 28) | (t >> 1);
    const bool odd = (t & 1);

    const uint32_t kLaneOff = (uint32_t)((lr * KSTRIDE + (lm >> 1) * 8 + (lm & 1) * 4) * 4);
    const uint32_t vLaneOff = (uint32_t)((((lm >> 1) * 8 + lr) * KSTRIDE + (lm & 1) * 4) * 4);

    int cur = 0;
    for (int s0 = 0; s0 < kend; s0 += 64) {
        CP_WAIT0();
        __syncthreads();
        if (s0 + 64 < kend) {
            attn_issue_kv(K, VT, sm, cur ^ 1, b, kh, s0 + 64, tid);
            CP_COMMIT();
        }

        if (s0 <= rowBase + 15) {
            uint32_t ks_base = (uint32_t)__cvta_generic_to_shared(
                sm + cur * KV_BUF_FLOATS + KS_OFF);
            uint32_t vs_base = (uint32_t)__cvta_generic_to_shared(
                sm + cur * KV_BUF_FLOATS + VS_OFF);

            // ---- S' = (Q*scale*log2e) @ K^T ----
            float sacc[8][4];
#pragma unroll
            for (int ni = 0; ni < 8; ni++) {
                sacc[ni][0] = 0.f; sacc[ni][1] = 0.f;
                sacc[ni][2] = 0.f; sacc[ni][3] = 0.f;
#pragma unroll
                for (int j = 0; j < 4; j++) {
                    uint32_t b0a, b1a, b0b, b1b;
                    ldsm4(b0a, b1a, b0b, b1b,
                          ks_base + (uint32_t)((ni * 8 * KSTRIDE + j * 16) * 4) + kLaneOff);
                    mma_tf32(sacc[ni][0], sacc[ni][1], sacc[ni][2], sacc[ni][3],
                             qa[2*j][0], qa[2*j][1], qa[2*j][2], qa[2*j][3], b0a, b1a);
                    mma_tf32(sacc[ni][0], sacc[ni][1], sacc[ni][2], sacc[ni][3],
                             qa[2*j+1][0], qa[2*j+1][1], qa[2*j+1][2], qa[2*j+1][3], b0b, b1b);
                }
            }

            // ---- causal mask ----
            if (s0 + 63 > rowBase) {
                int r0 = rowBase + g;
                int r1 = r0 + 8;
#pragma unroll
                for (int ni = 0; ni < 8; ni++) {
                    int c = s0 + ni * 8 + 2 * t;
                    if (c > r0)     sacc[ni][0] = -1e30f;
                    if (c + 1 > r0) sacc[ni][1] = -1e30f;
                    if (c > r1)     sacc[ni][2] = -1e30f;
                    if (c + 1 > r1) sacc[ni][3] = -1e30f;
                }
            }

            // ---- online softmax (base 2) ----
            float mx0 = -1e30f, mx1 = -1e30f;
#pragma unroll
            for (int ni = 0; ni < 8; ni++) {
                mx0 = fmaxf(mx0, fmaxf(sacc[ni][0], sacc[ni][1]));
                mx1 = fmaxf(mx1, fmaxf(sacc[ni][2], sacc[ni][3]));
            }
            mx0 = fmaxf(mx0, __shfl_xor_sync(0xffffffffu, mx0, 1));
            mx0 = fmaxf(mx0, __shfl_xor_sync(0xffffffffu, mx0, 2));
            mx1 = fmaxf(mx1, __shfl_xor_sync(0xffffffffu, mx1, 1));
            mx1 = fmaxf(mx1, __shfl_xor_sync(0xffffffffu, mx1, 2));

            float mn0 = fmaxf(m0, mx0), mn1 = fmaxf(m1, mx1);
            float cr0 = ex2(m0 - mn0), cr1 = ex2(m1 - mn1);
            m0 = mn0; m1 = mn1;
            l0 *= cr0; l1 *= cr1;
#pragma unroll
            for (int ni = 0; ni < 8; ni++) {
                oacc[ni][0] *= cr0; oacc[ni][1] *= cr0;
                oacc[ni][2] *= cr1; oacc[ni][3] *= cr1;
            }
#pragma unroll
            for (int ni = 0; ni < 8; ni++) {
                sacc[ni][0] = ex2(sacc[ni][0] - m0);
                sacc[ni][1] = ex2(sacc[ni][1] - m0);
                sacc[ni][2] = ex2(sacc[ni][2] - m1);
                sacc[ni][3] = ex2(sacc[ni][3] - m1);
                l0 += sacc[ni][0] + sacc[ni][1];
                l1 += sacc[ni][2] + sacc[ni][3];
            }

            // ---- O += P @ V (shuffle relayout C-frag -> A-frag) ----
#pragma unroll
            for (int kc = 0; kc < 8; kc++) {
                float v00 = __shfl_sync(0xffffffffu, sacc[kc][0], srcA);
                float v01 = __shfl_sync(0xffffffffu, sacc[kc][1], srcA);
                float v10 = __shfl_sync(0xffffffffu, sacc[kc][2], srcA);
                float v11 = __shfl_sync(0xffffffffu, sacc[kc][3], srcA);
                float w00 = __shfl_sync(0xffffffffu, sacc[kc][0], srcA + 2);
                float w01 = __shfl_sync(0xffffffffu, sacc[kc][1], srcA + 2);
                float w10 = __shfl_sync(0xffffffffu, sacc[kc][2], srcA + 2);
                float w11 = __shfl_sync(0xffffffffu, sacc[kc][3], srcA + 2);
                uint32_t a0 = f2tf32(odd ? v01 : v00);
                uint32_t a1 = f2tf32(odd ? v11 : v10);
                uint32_t a2 = f2tf32(odd ? w01 : w00);
                uint32_t a3 = f2tf32(odd ? w11 : w10);
#pragma unroll
                for (int jj = 0; jj < 4; jj++) {
                    uint32_t c0, c1, c2, c3;
                    ldsm4(c0, c1, c2, c3,
                          vs_base + (uint32_t)((jj * 16 * KSTRIDE + kc * 8) * 4) + vLaneOff);
                    mma_tf32(oacc[2*jj][0], oacc[2*jj][1], oacc[2*jj][2], oacc[2*jj][3],
                             a0, a1, a2, a3, c0, c1);
                    mma_tf32(oacc[2*jj+1][0], oacc[2*jj+1][1], oacc[2*jj+1][2], oacc[2*jj+1][3],
                             a0, a1, a2, a3, c2, c3);
                }
            }
        }
        cur ^= 1;
    }

    l0 += __shfl_xor_sync(0xffffffffu, l0, 1);
    l0 += __shfl_xor_sync(0xffffffffu, l0, 2);
    l1 += __shfl_xor_sync(0xffffffffu, l1, 1);
    l1 += __shfl_xor_sync(0xffffffffu, l1, 2);
    float inv0 = 1.f / l0, inv1 = 1.f / l1;

    int R0 = rowBase + g;
    float* o0 = O + (size_t)(b * TT + R0) * DD + h * DH;
    float* o1 = o0 + (size_t)8 * DD;
#pragma unroll
    for (int ni = 0; ni < 8; ni++) {
        *(float2*)(o0 + ni * 8 + 2 * t) =
            make_float2(rtf(oacc[ni][0] * inv0), rtf(oacc[ni][1] * inv0));
        *(float2*)(o1 + ni * 8 + 2 * t) =
            make_float2(rtf(oacc[ni][2] * inv1), rtf(oacc[ni][3] * inv1));
    }
}

// ---------------------------------------------------------------------------
// Launch
// ---------------------------------------------------------------------------
extern "C" void kernel_launch(void* const* d_in, const int* in_sizes, int n_in,
                              void* d_out, int out_size)
{
    const float* x  = (const float*)d_in[0];
    const float* Wq = (const float*)d_in[1];
    const float* Wk = (const float*)d_in[2];
    const float* Wv = (const float*)d_in[3];
    const float* Wo = (const float*)d_in[4];
    float* out = (float*)d_out;

    float *q, *k, *v, *vt, *ctx, *xr, *wqr, *wkr, *wvr, *wor;
    cudaGetSymbolAddress((void**)&q,   g_q);
    cudaGetSymbolAddress((void**)&k,   g_k);
    cudaGetSymbolAddress((void**)&v,   g_v);
    cudaGetSymbolAddress((void**)&vt,  g_vt);
    cudaGetSymbolAddress((void**)&ctx, g_ctx);
    cudaGetSymbolAddress((void**)&xr,  g_xr);
    cudaGetSymbolAddress((void**)&wqr, g_wqr);
    cudaGetSymbolAddress((void**)&wkr, g_wkr);
    cudaGetSymbolAddress((void**)&wvr, g_wvr);
    cudaGetSymbolAddress((void**)&wor, g_wor);

    static bool attr_set = false;
    if (!attr_set) {
        cudaFuncSetAttribute(flash_attn_tc,
                             cudaFuncAttributeMaxDynamicSharedMemorySize,
                             2 * KV_BUF_FLOATS * (int)sizeof(float));
        attr_set = true;
    }

    const int M = BB * TT;   // 4096

    trig_init<<<(TT * 32 + 255) / 256, 256>>>();

    // merged tf32 round-copy of all inputs (one launch)
    round_all<<<1184, 256>>>((const float4*)x,  (const float4*)Wq,
                             (const float4*)Wk, (const float4*)Wv,
                             (const float4*)Wo,
                             (float4*)xr,  (float4*)wqr,
                             (float4*)wkr, (float4*)wvr, (float4*)wor);

    // Fused QKV projection
    gemm_qkv<<<dim3(24, M / GBM), 256>>>(xr, wqr, wkr, wvr, q, k, v);

    // RoPE (q, k) + V transpose/round
    {
        int totq = M * NH * 8;
        int totk = M * NKV * 8;
        int totv = M * NKV * 16;
        rope_round<<<(totq + totk + totv + 255) / 256, 256>>>(q, k, v, vt,
                                                              totq, totk, totv);
    }

    // Attention
    flash_attn_tc<<<dim3(TT / 128, NH, BB), 256,
                    2 * KV_BUF_FLOATS * sizeof(float)>>>(q, k, vt, ctx);

    // Output projection
    gemm_tf32<<<dim3(DD / GBN, M / GBM), 256>>>(M, DD, DD, ctx, wor, out);
}